// round 12
// baseline (speedup 1.0000x reference)
#include <cuda_runtime.h>
#include <math.h>

#define NB 16
#define NH 320
#define NW 320
#define NPIX (NB * NH * NW)
#define NWORDS 10            // 320 / 32
#define ROWS1 4              // rows per pass-1 block
#define SENTINEL 20000       // "no seed in this row" distance stand-in
#define BIGI (1 << 29)
#define INV_N (1.0f / (float)NPIX)

// Packed pass-1 outputs.
//  g_code2: short2 per pixel = (pred code, target code); sign = mask bit, |.| = row dist.
//  g_bits : row ballot words per field/image/row (for pass2 neighborhood resolve).
__device__ short2 g_code2[NPIX];
__device__ unsigned int g_bits[2][NB * NH * NWORDS];
__device__ int g_hasfg[2][NB];   // zero-init at load; OR idempotent across replays

// Nearest set bit to center (bit 32) of a 64-bit window. Returns -1 if none.
__device__ __forceinline__ int ndist(unsigned long long v) {
    if (!v) return -1;
    unsigned long long t = v >> 32;
    int dR = t ? (__ffsll((long long)t) - 1) : 1000;
    unsigned long long u = v << 32;
    int dL = u ? (__clzll((long long)u) + 1) : 1000;
    return min(dR, dL);
}

// Rare fallback: nearest bit equal to want_one at distance > 32.
__device__ int far_search(const unsigned int* w, int x, int want_one) {
    for (int d = 33; d < NW; d++) {
        int l = x - d, r = x + d;
        if (l >= 0) { int b = (w[l >> 5] >> (l & 31)) & 1; if (b == want_one) return d; }
        if (r < NW) { int b = (w[r >> 5] >> (r & 31)) & 1; if (b == want_one) return d; }
    }
    return SENTINEL;
}

__device__ __forceinline__ unsigned long long mkwin(const unsigned int* w, int c, int o) {
    unsigned int w0 = (c > 0) ? w[c - 1] : 0u;
    unsigned int w1 = w[c];
    unsigned int w2 = (c < NWORDS - 1) ? w[c + 1] : 0u;
    unsigned long long lo = (unsigned long long)w0 | ((unsigned long long)w1 << 32);
    unsigned long long win = lo >> o;
    if (o) win |= (unsigned long long)w2 << (64 - o);
    return win;
}

__device__ __forceinline__ int row_code(const unsigned int* w, int c, int o,
                                        unsigned long long validw, int bit, int x) {
    unsigned long long win = mkwin(w, c, o);
    if (bit) {                       // fg pixel: nearest 0
        int d = ndist((~win) & validw);
        if (d < 0) d = far_search(w, x, 0);
        return d;
    } else {                         // bg pixel: nearest 1
        int d = ndist(win & validw);
        if (d < 0) d = far_search(w, x, 1);
        return -d;
    }
}

// Pass 1: one block = ROWS1 rows of one image. 320 threads.
__global__ void __launch_bounds__(NW)
hd_pass1_kernel(const float* __restrict__ pred,
                const float* __restrict__ tgt,
                float* __restrict__ out) {
    const int y0 = blockIdx.x * ROWS1;
    const int n = blockIdx.y;
    const int x = threadIdx.x;

    if (blockIdx.x == 0 && n == 0 && x == 0) out[0] = 0.0f;

    __shared__ unsigned int wp[ROWS1][NWORDS];
    __shared__ unsigned int wt[ROWS1][NWORDS];

    const int base = (n * NH + y0) * NW + x;

    float pv[ROWS1], tv[ROWS1];
#pragma unroll
    for (int k = 0; k < ROWS1; k++) {
        pv[k] = pred[base + k * NW];
        tv[k] = tgt[base + k * NW];
    }

    const int lane = x & 31, wid = x >> 5;
    int bp[ROWS1], bt[ROWS1];
#pragma unroll
    for (int k = 0; k < ROWS1; k++) {
        bp[k] = (pv[k] > 0.5f) ? 1 : 0;
        bt[k] = (tv[k] > 0.5f) ? 1 : 0;
        const unsigned int balp = __ballot_sync(0xffffffffu, bp[k]);
        const unsigned int balt = __ballot_sync(0xffffffffu, bt[k]);
        if (lane == 0) {
            wp[k][wid] = balp;
            wt[k][wid] = balt;
            const int rowidx = (n * NH + y0 + k) * NWORDS + wid;
            g_bits[0][rowidx] = balp;      // persist for pass2 neighborhood resolve
            g_bits[1][rowidx] = balt;
        }
    }

    __syncthreads();   // publish all rows

    if (x == 0) {
        unsigned int pa = 0u, ta = 0u;
#pragma unroll
        for (int k = 0; k < ROWS1; k++)
#pragma unroll
            for (int i = 0; i < NWORDS; i++) { pa |= wp[k][i]; ta |= wt[k][i]; }
        if (pa) atomicOr(&g_hasfg[0][n], 1);
        if (ta) atomicOr(&g_hasfg[1][n], 1);
    }

    unsigned long long validw = ~0ULL;
    if (x < 32)  validw <<= (32 - x);
    if (x > 288) validw &= (~0ULL >> (x - 288));

#pragma unroll
    for (int k = 0; k < ROWS1; k++) {
        const int cP = row_code(wp[k], wid, lane, validw, bp[k], x);
        const int cT = row_code(wt[k], wid, lane, validw, bt[k], x);
        g_code2[base + k * NW] = make_short2((short)cP, (short)cT);
    }
}

// Pass 2 + fused loss. One block = one row, 320 threads.
// Bit-parallel resolve over rows y-1..y+1; code-walk tail only if best > 4 (rare).
__global__ void __launch_bounds__(NW)
hd_pass2_kernel(const float* __restrict__ pred,
                const float* __restrict__ tgt,
                float* __restrict__ out) {
    const int y = blockIdx.x;
    const int n = blockIdx.y;
    const int x = threadIdx.x;

    const int plane = n * NH * NW;
    const int idx = plane + y * NW + x;

    const float pv = pred[idx];      // issue early
    const float tv = tgt[idx];

    // Stage rows y-1, y, y+1 of both fields' ballot words.
    __shared__ unsigned int sb[2][3][NWORDS];
    if (x < 2 * 3 * NWORDS) {
        const int f = x / (3 * NWORDS);
        const int rem = x % (3 * NWORDS);
        const int ry = rem / NWORDS;
        const int w = rem % NWORDS;
        const int yy = y - 1 + ry;
        sb[f][ry][w] = (yy >= 0 && yy < NH) ? g_bits[f][(n * NH + yy) * NWORDS + w] : 0u;
    }
    __syncthreads();

    const int c = x >> 5, o = x & 31;
    unsigned long long validw = ~0ULL;
    if (x < 32)  validw <<= (32 - x);
    if (x > 288) validw &= (~0ULL >> (x - 288));
    const bool hasUp = (y > 0);
    const bool hasDn = (y < NH - 1);

    int bestP, bestT, sP, sT;
    {
        const unsigned long long winM = mkwin(sb[0][1], c, o);
        const int b = (int)((winM >> 32) & 1ULL);
        sP = b ? 1 : -1;
        const unsigned long long inv = b ? ~0ULL : 0ULL;
        const int a  = ndist((winM ^ inv) & validw);
        const int dU = hasUp ? ndist((mkwin(sb[0][0], c, o) ^ inv) & validw) : -1;
        const int dD = hasDn ? ndist((mkwin(sb[0][2], c, o) ^ inv) & validw) : -1;
        int best = (a < 0) ? BIGI : a * a;
        if (dU >= 0) best = min(best, 1 + dU * dU);
        if (dD >= 0) best = min(best, 1 + dD * dD);
        bestP = best;
    }
    {
        const unsigned long long winM = mkwin(sb[1][1], c, o);
        const int b = (int)((winM >> 32) & 1ULL);
        sT = b ? 1 : -1;
        const unsigned long long inv = b ? ~0ULL : 0ULL;
        const int a  = ndist((winM ^ inv) & validw);
        const int dU = hasUp ? ndist((mkwin(sb[1][0], c, o) ^ inv) & validw) : -1;
        const int dD = hasDn ? ndist((mkwin(sb[1][2], c, o) ^ inv) & validw) : -1;
        int best = (a < 0) ? BIGI : a * a;
        if (dU >= 0) best = min(best, 1 + dU * dU);
        if (dD >= 0) best = min(best, 1 + dD * dD);
        bestT = best;
    }

    // Rows |dy| >= 2 contribute >= 4, so best <= 4 is exact. Rare tail otherwise.
    if (__any_sync(0xffffffffu, max(bestP, bestT) > 4)) {
        const short2 c0 = g_code2[idx];            // exact own-row dists (incl. >31)
        const int aP = abs((int)c0.x), aT = abs((int)c0.y);
        bestP = min(bestP, aP * aP);
        bestT = min(bestT, aT * aT);
        int bmax = max(bestP, bestT);

        const int rUp = y;
        const int rDn = NH - 1 - y;
        const short2* colbase = g_code2 + plane + x;

        int r = 1, r2 = 1;
        while (r < NH && __any_sync(0xffffffffu, r2 < bmax)) {
            if (r <= rUp) {
                const short2 v = colbase[(y - r) * NW];
                const int dP = max(sP * (int)v.x, 0);
                const int dT = max(sT * (int)v.y, 0);
                bestP = min(bestP, dP * dP + r2);
                bestT = min(bestT, dT * dT + r2);
            }
            if (r <= rDn) {
                const short2 v = colbase[(y + r) * NW];
                const int dP = max(sP * (int)v.x, 0);
                const int dT = max(sT * (int)v.y, 0);
                bestP = min(bestP, dP * dP + r2);
                bestT = min(bestT, dT * dT + r2);
            }
            bmax = max(bestP, bestT);
            r += 1;
            r2 += (r << 1) - 1;
        }
    }

    const float dt2p = g_hasfg[0][n] ? (float)bestP : 0.0f;
    const float dt2t = g_hasfg[1][n] ? (float)bestT : 0.0f;

    const float e = pv - tv;
    float v = e * e * (dt2p + dt2t) * INV_N;

#pragma unroll
    for (int off = 16; off > 0; off >>= 1)
        v += __shfl_down_sync(0xffffffffu, v, off);

    __shared__ float wsum[NW / 32];
    const int lane = x & 31;
    const int wid = x >> 5;
    if (lane == 0) wsum[wid] = v;
    __syncthreads();
    if (x == 0) {
        float s = 0.0f;
#pragma unroll
        for (int i = 0; i < NW / 32; i++) s += wsum[i];
        atomicAdd(out, s);
    }
}

extern "C" void kernel_launch(void* const* d_in, const int* in_sizes, int n_in,
                              void* d_out, int out_size) {
    const float* pred = (const float*)d_in[0];
    const float* tgt  = (const float*)d_in[1];
    float* out = (float*)d_out;

    dim3 grid1(NH / ROWS1, NB);
    hd_pass1_kernel<<<grid1, NW>>>(pred, tgt, out);
    dim3 grid2(NH, NB);
    hd_pass2_kernel<<<grid2, NW>>>(pred, tgt, out);
}

// round 15
// speedup vs baseline: 1.3513x; 1.3513x over previous
#include <cuda_runtime.h>
#include <math.h>

#define NB 16
#define NH 320
#define NW 320
#define NPIX (NB * NH * NW)
#define NWORDS 10            // 320 / 32
#define ROWS1 4              // rows per pass-1 block
#define SENTINEL 20000       // "no seed in this row" distance stand-in
#define RCAP 34              // static-walk cap; dynamic tail beyond (pathological only)
#define INV_N (1.0f / (float)NPIX)

// Packed pass-1 output: short2 per pixel = (pred code, target code).
//  code > 0 : pixel is fg (mask=1); code = dist to nearest 0 in row
//  code < 0 : pixel is bg (mask=0); -code = dist to nearest 1 in row
__device__ short2 g_code2[NPIX];
__device__ int g_hasfg[2][NB];   // zero-init at load; OR idempotent across replays

// Nearest set bit to center (bit 32) of a 64-bit window. Returns -1 if none.
__device__ __forceinline__ int ndist(unsigned long long v) {
    if (!v) return -1;
    unsigned long long t = v >> 32;
    int dR = t ? (__ffsll((long long)t) - 1) : 1000;
    unsigned long long u = v << 32;
    int dL = u ? (__clzll((long long)u) + 1) : 1000;
    return min(dR, dL);
}

// Rare fallback: nearest bit equal to want_one at distance > 32.
__device__ int far_search(const unsigned int* w, int x, int want_one) {
    for (int d = 33; d < NW; d++) {
        int l = x - d, r = x + d;
        if (l >= 0) { int b = (w[l >> 5] >> (l & 31)) & 1; if (b == want_one) return d; }
        if (r < NW) { int b = (w[r >> 5] >> (r & 31)) & 1; if (b == want_one) return d; }
    }
    return SENTINEL;
}

__device__ __forceinline__ int row_code(const unsigned int* w, int c, int o,
                                        unsigned long long validw, int bit, int x) {
    unsigned int w0 = (c > 0) ? w[c - 1] : 0u;
    unsigned int w1 = w[c];
    unsigned int w2 = (c < NWORDS - 1) ? w[c + 1] : 0u;
    unsigned long long lo = (unsigned long long)w0 | ((unsigned long long)w1 << 32);
    unsigned long long win = lo >> o;
    if (o) win |= (unsigned long long)w2 << (64 - o);
    if (bit) {                       // fg pixel: nearest 0
        int d = ndist((~win) & validw);
        if (d < 0) d = far_search(w, x, 0);
        return d;
    } else {                         // bg pixel: nearest 1
        int d = ndist(win & validw);
        if (d < 0) d = far_search(w, x, 1);
        return -d;
    }
}

// Pass 1: one block = ROWS1 rows of one image. 320 threads.
__global__ void __launch_bounds__(NW)
hd_pass1_kernel(const float* __restrict__ pred,
                const float* __restrict__ tgt,
                float* __restrict__ out) {
    const int y0 = blockIdx.x * ROWS1;
    const int n = blockIdx.y;
    const int x = threadIdx.x;

    if (blockIdx.x == 0 && n == 0 && x == 0) out[0] = 0.0f;

    __shared__ unsigned int wp[ROWS1][NWORDS];
    __shared__ unsigned int wt[ROWS1][NWORDS];

    const int base = (n * NH + y0) * NW + x;

    // Front-load all inputs: 8 independent global loads, one latency exposure.
    float pv[ROWS1], tv[ROWS1];
#pragma unroll
    for (int k = 0; k < ROWS1; k++) {
        pv[k] = pred[base + k * NW];
        tv[k] = tgt[base + k * NW];
    }

    const int lane = x & 31, wid = x >> 5;
    int bp[ROWS1], bt[ROWS1];
#pragma unroll
    for (int k = 0; k < ROWS1; k++) {
        bp[k] = (pv[k] > 0.5f) ? 1 : 0;
        bt[k] = (tv[k] > 0.5f) ? 1 : 0;
        const unsigned int balp = __ballot_sync(0xffffffffu, bp[k]);
        const unsigned int balt = __ballot_sync(0xffffffffu, bt[k]);
        if (lane == 0) { wp[k][wid] = balp; wt[k][wid] = balt; }
    }

    __syncthreads();   // publish all rows

    if (x == 0) {
        unsigned int pa = 0u, ta = 0u;
#pragma unroll
        for (int k = 0; k < ROWS1; k++)
#pragma unroll
            for (int i = 0; i < NWORDS; i++) { pa |= wp[k][i]; ta |= wt[k][i]; }
        if (pa) atomicOr(&g_hasfg[0][n], 1);
        if (ta) atomicOr(&g_hasfg[1][n], 1);
    }

    unsigned long long validw = ~0ULL;
    if (x < 32)  validw <<= (32 - x);
    if (x > 288) validw &= (~0ULL >> (x - 288));

#pragma unroll
    for (int k = 0; k < ROWS1; k++) {
        const int cP = row_code(wp[k], wid, lane, validw, bp[k], x);
        const int cT = row_code(wt[k], wid, lane, validw, bt[k], x);
        g_code2[base + k * NW] = make_short2((short)cP, (short)cT);
    }
}

// Pass 2 + fused loss. One block = one row of one image, 320 threads.
// Static-bound walk: trip count depends only on the center code, so neighbor
// loads are address-independent across iterations and pipeline fully.
__global__ void __launch_bounds__(NW)
hd_pass2_kernel(const float* __restrict__ pred,
                const float* __restrict__ tgt,
                float* __restrict__ out) {
    const int y = blockIdx.x;
    const int n = blockIdx.y;
    const int x = threadIdx.x;

    const int plane = n * NH * NW;
    const int idx = plane + y * NW + x;

    const float pv = pred[idx];
    const float tv = tgt[idx];
    const short2 c0 = g_code2[idx];

    const int cp = c0.x, ct = c0.y;
    const int sP = (cp > 0) ? 1 : -1;     // active field selector per column
    const int sT = (ct > 0) ? 1 : -1;
    const int aP = abs(cp), aT = abs(ct);
    int bestP = aP * aP;
    int bestT = aT * aT;

    const int rUp = y;            // up neighbor valid while r <= r Up
    const int rDn = NH - 1 - y;   // down neighbor valid while r <= rDn
    const short2* colbase = g_code2 + plane + x;

    // Exact bound: only r < max(aP,aT) can improve either field.
    const int aMax = min(max(aP, aT), RCAP);

#pragma unroll 2
    for (int r = 1; r < aMax; r++) {
        const int r2 = r * r;
        if (r <= rUp) {
            const short2 v = colbase[(y - r) * NW];
            const int dP = max(sP * (int)v.x, 0);
            const int dT = max(sT * (int)v.y, 0);
            bestP = min(bestP, dP * dP + r2);
            bestT = min(bestT, dT * dT + r2);
        }
        if (r <= rDn) {
            const short2 v = colbase[(y + r) * NW];
            const int dP = max(sP * (int)v.x, 0);
            const int dT = max(sT * (int)v.y, 0);
            bestP = min(bestP, dP * dP + r2);
            bestT = min(bestT, dT * dT + r2);
        }
    }

    // Pathological tail (a >= RCAP): dynamic, warp-uniform. Never runs on noise data.
    if (__any_sync(0xffffffffu, max(aP, aT) >= RCAP)) {
        int bmax = max(bestP, bestT);
        int r = RCAP, r2 = RCAP * RCAP;
        while (r < NH && __any_sync(0xffffffffu, r2 < bmax)) {
            if (r <= rUp) {
                const short2 v = colbase[(y - r) * NW];
                const int dP = max(sP * (int)v.x, 0);
                const int dT = max(sT * (int)v.y, 0);
                bestP = min(bestP, dP * dP + r2);
                bestT = min(bestT, dT * dT + r2);
            }
            if (r <= rDn) {
                const short2 v = colbase[(y + r) * NW];
                const int dP = max(sP * (int)v.x, 0);
                const int dT = max(sT * (int)v.y, 0);
                bestP = min(bestP, dP * dP + r2);
                bestT = min(bestT, dT * dT + r2);
            }
            bmax = max(bestP, bestT);
            r += 1;
            r2 += (r << 1) - 1;
        }
    }

    // dt^2 = active-field squared EDT (complementary field is 0 at every pixel)
    const float dt2p = g_hasfg[0][n] ? (float)bestP : 0.0f;
    const float dt2t = g_hasfg[1][n] ? (float)bestT : 0.0f;

    const float e = pv - tv;
    float v = e * e * (dt2p + dt2t) * INV_N;

#pragma unroll
    for (int off = 16; off > 0; off >>= 1)
        v += __shfl_down_sync(0xffffffffu, v, off);

    __shared__ float wsum[NW / 32];
    const int lane = x & 31;
    const int wid = x >> 5;
    if (lane == 0) wsum[wid] = v;
    __syncthreads();
    if (x == 0) {
        float s = 0.0f;
#pragma unroll
        for (int i = 0; i < NW / 32; i++) s += wsum[i];
        atomicAdd(out, s);
    }
}

extern "C" void kernel_launch(void* const* d_in, const int* in_sizes, int n_in,
                              void* d_out, int out_size) {
    const float* pred = (const float*)d_in[0];
    const float* tgt  = (const float*)d_in[1];
    float* out = (float*)d_out;

    dim3 grid1(NH / ROWS1, NB);
    hd_pass1_kernel<<<grid1, NW>>>(pred, tgt, out);
    dim3 grid2(NH, NB);
    hd_pass2_kernel<<<grid2, NW>>>(pred, tgt, out);
}

// round 16
// speedup vs baseline: 1.4743x; 1.0910x over previous
#include <cuda_runtime.h>
#include <math.h>

#define NB 16
#define NH 320
#define NW 320
#define NPIX (NB * NH * NW)
#define NWORDS 10            // 320 / 32
#define ROWS1 4              // rows per pass-1 block
#define SENTINEL 20000       // "no seed in this row" distance stand-in
#define INV_N (1.0f / (float)NPIX)

// Packed pass-1 output: short2 per pixel = (pred code, target code).
//  code > 0 : pixel is fg (mask=1); code = dist to nearest 0 in row
//  code < 0 : pixel is bg (mask=0); -code = dist to nearest 1 in row
__device__ short2 g_code2[NPIX];
__device__ int g_hasfg[2][NB];   // zero-init at load; OR idempotent across replays

// Nearest set bit to center (bit 32) of a 64-bit window. Returns -1 if none.
__device__ __forceinline__ int ndist(unsigned long long v) {
    if (!v) return -1;
    unsigned long long t = v >> 32;
    int dR = t ? (__ffsll((long long)t) - 1) : 1000;
    unsigned long long u = v << 32;
    int dL = u ? (__clzll((long long)u) + 1) : 1000;
    return min(dR, dL);
}

// Rare fallback: nearest bit equal to want_one at distance > 32.
__device__ int far_search(const unsigned int* w, int x, int want_one) {
    for (int d = 33; d < NW; d++) {
        int l = x - d, r = x + d;
        if (l >= 0) { int b = (w[l >> 5] >> (l & 31)) & 1; if (b == want_one) return d; }
        if (r < NW) { int b = (w[r >> 5] >> (r & 31)) & 1; if (b == want_one) return d; }
    }
    return SENTINEL;
}

__device__ __forceinline__ int row_code(const unsigned int* w, int c, int o,
                                        unsigned long long validw, int bit, int x) {
    unsigned int w0 = (c > 0) ? w[c - 1] : 0u;
    unsigned int w1 = w[c];
    unsigned int w2 = (c < NWORDS - 1) ? w[c + 1] : 0u;
    unsigned long long lo = (unsigned long long)w0 | ((unsigned long long)w1 << 32);
    unsigned long long win = lo >> o;
    if (o) win |= (unsigned long long)w2 << (64 - o);
    if (bit) {                       // fg pixel: nearest 0
        int d = ndist((~win) & validw);
        if (d < 0) d = far_search(w, x, 0);
        return d;
    } else {                         // bg pixel: nearest 1
        int d = ndist(win & validw);
        if (d < 0) d = far_search(w, x, 1);
        return -d;
    }
}

// Pass 1: one block = ROWS1 rows of one image. 320 threads.
__global__ void __launch_bounds__(NW)
hd_pass1_kernel(const float* __restrict__ pred,
                const float* __restrict__ tgt,
                float* __restrict__ out) {
    const int y0 = blockIdx.x * ROWS1;
    const int n = blockIdx.y;
    const int x = threadIdx.x;

    if (blockIdx.x == 0 && n == 0 && x == 0) out[0] = 0.0f;

    __shared__ unsigned int wp[ROWS1][NWORDS];
    __shared__ unsigned int wt[ROWS1][NWORDS];

    const int base = (n * NH + y0) * NW + x;

    // Front-load all inputs: 8 independent global loads, one latency exposure.
    float pv[ROWS1], tv[ROWS1];
#pragma unroll
    for (int k = 0; k < ROWS1; k++) {
        pv[k] = pred[base + k * NW];
        tv[k] = tgt[base + k * NW];
    }

    const int lane = x & 31, wid = x >> 5;
    int bp[ROWS1], bt[ROWS1];
#pragma unroll
    for (int k = 0; k < ROWS1; k++) {
        bp[k] = (pv[k] > 0.5f) ? 1 : 0;
        bt[k] = (tv[k] > 0.5f) ? 1 : 0;
        const unsigned int balp = __ballot_sync(0xffffffffu, bp[k]);
        const unsigned int balt = __ballot_sync(0xffffffffu, bt[k]);
        if (lane == 0) { wp[k][wid] = balp; wt[k][wid] = balt; }
    }

    __syncthreads();   // publish all rows

    if (x == 0) {
        unsigned int pa = 0u, ta = 0u;
#pragma unroll
        for (int k = 0; k < ROWS1; k++)
#pragma unroll
            for (int i = 0; i < NWORDS; i++) { pa |= wp[k][i]; ta |= wt[k][i]; }
        if (pa) atomicOr(&g_hasfg[0][n], 1);
        if (ta) atomicOr(&g_hasfg[1][n], 1);
    }

    unsigned long long validw = ~0ULL;
    if (x < 32)  validw <<= (32 - x);
    if (x > 288) validw &= (~0ULL >> (x - 288));

#pragma unroll
    for (int k = 0; k < ROWS1; k++) {
        const int cP = row_code(wp[k], wid, lane, validw, bp[k], x);
        const int cT = row_code(wt[k], wid, lane, validw, bt[k], x);
        g_code2[base + k * NW] = make_short2((short)cP, (short)cT);
    }
}

// Apply the candidate from row y+dy (guarded) to both fields.
__device__ __forceinline__ void apply_row(const short2* colbase, int y, int dy,
                                          bool valid, int sP, int sT, int r2,
                                          int& bestP, int& bestT) {
    if (valid) {
        const short2 v = colbase[(y + dy) * NW];
        const int dP = max(sP * (int)v.x, 0);
        const int dT = max(sT * (int)v.y, 0);
        bestP = min(bestP, dP * dP + r2);
        bestT = min(bestT, dT * dT + r2);
    }
}

// Pass 2 + fused loss. One block = one row of one image, 320 threads.
// Shrinking-bound walk, TWO radii per iteration: 4 independent loads issued
// together, so the dependent chain (load -> bmax -> next trip) is half as deep.
__global__ void __launch_bounds__(NW)
hd_pass2_kernel(const float* __restrict__ pred,
                const float* __restrict__ tgt,
                float* __restrict__ out) {
    const int y = blockIdx.x;
    const int n = blockIdx.y;
    const int x = threadIdx.x;

    const int plane = n * NH * NW;
    const int idx = plane + y * NW + x;

    const float pv = pred[idx];
    const float tv = tgt[idx];
    const short2 c0 = g_code2[idx];

    const int cp = c0.x, ct = c0.y;
    const int sP = (cp > 0) ? 1 : -1;     // active field selector per column
    const int sT = (ct > 0) ? 1 : -1;
    const int aP = abs(cp), aT = abs(ct);
    int bestP = aP * aP;
    int bestT = aT * aT;
    int bmax = max(bestP, bestT);

    const int rUp = y;            // up neighbor valid while r <= rUp
    const int rDn = NH - 1 - y;   // down neighbor valid while r <= rDn
    const short2* colbase = g_code2 + plane + x;

    int r = 1;
    while (r * r < bmax && r < NH) {
        const int r2a = r * r;
        const int rb = r + 1;
        const int r2b = rb * rb;
        // 4 address-independent loads; issued back-to-back before any use.
        apply_row(colbase, y, -r,  r  <= rUp, sP, sT, r2a, bestP, bestT);
        apply_row(colbase, y,  r,  r  <= rDn, sP, sT, r2a, bestP, bestT);
        apply_row(colbase, y, -rb, rb <= rUp, sP, sT, r2b, bestP, bestT);
        apply_row(colbase, y,  rb, rb <= rDn, sP, sT, r2b, bestP, bestT);
        bmax = max(bestP, bestT);
        r += 2;
    }

    // dt^2 = active-field squared EDT (complementary field is 0 at every pixel)
    const float dt2p = g_hasfg[0][n] ? (float)bestP : 0.0f;
    const float dt2t = g_hasfg[1][n] ? (float)bestT : 0.0f;

    const float e = pv - tv;
    float v = e * e * (dt2p + dt2t) * INV_N;

#pragma unroll
    for (int off = 16; off > 0; off >>= 1)
        v += __shfl_down_sync(0xffffffffu, v, off);

    __shared__ float wsum[NW / 32];
    const int lane = x & 31;
    const int wid = x >> 5;
    if (lane == 0) wsum[wid] = v;
    __syncthreads();
    if (x == 0) {
        float s = 0.0f;
#pragma unroll
        for (int i = 0; i < NW / 32; i++) s += wsum[i];
        atomicAdd(out, s);
    }
}

extern "C" void kernel_launch(void* const* d_in, const int* in_sizes, int n_in,
                              void* d_out, int out_size) {
    const float* pred = (const float*)d_in[0];
    const float* tgt  = (const float*)d_in[1];
    float* out = (float*)d_out;

    dim3 grid1(NH / ROWS1, NB);
    hd_pass1_kernel<<<grid1, NW>>>(pred, tgt, out);
    dim3 grid2(NH, NB);
    hd_pass2_kernel<<<grid2, NW>>>(pred, tgt, out);
}

// round 17
// speedup vs baseline: 1.7121x; 1.1613x over previous
#include <cuda_runtime.h>
#include <math.h>

#define NB 16
#define NH 320
#define NW 320
#define NPIX (NB * NH * NW)
#define NWORDS 10            // 320 / 32
#define ROWS1 4              // rows per pass-1 block
#define ROWS2 4              // rows per pass-2 block
#define SENTINEL 20000       // "no seed in this row" distance stand-in
#define INV_N (1.0f / (float)NPIX)

// Packed pass-1 output: short2 per pixel = (pred code, target code).
//  code > 0 : pixel is fg (mask=1); code = dist to nearest 0 in row
//  code < 0 : pixel is bg (mask=0); -code = dist to nearest 1 in row
__device__ short2 g_code2[NPIX];
__device__ int g_hasfg[2][NB];   // zero-init at load; OR idempotent across replays

// Nearest set bit to center (bit 32) of a 64-bit window. Returns -1 if none.
__device__ __forceinline__ int ndist(unsigned long long v) {
    if (!v) return -1;
    unsigned long long t = v >> 32;
    int dR = t ? (__ffsll((long long)t) - 1) : 1000;
    unsigned long long u = v << 32;
    int dL = u ? (__clzll((long long)u) + 1) : 1000;
    return min(dR, dL);
}

// Rare fallback: nearest bit equal to want_one at distance > 32.
__device__ int far_search(const unsigned int* w, int x, int want_one) {
    for (int d = 33; d < NW; d++) {
        int l = x - d, r = x + d;
        if (l >= 0) { int b = (w[l >> 5] >> (l & 31)) & 1; if (b == want_one) return d; }
        if (r < NW) { int b = (w[r >> 5] >> (r & 31)) & 1; if (b == want_one) return d; }
    }
    return SENTINEL;
}

__device__ __forceinline__ int row_code(const unsigned int* w, int c, int o,
                                        unsigned long long validw, int bit, int x) {
    unsigned int w0 = (c > 0) ? w[c - 1] : 0u;
    unsigned int w1 = w[c];
    unsigned int w2 = (c < NWORDS - 1) ? w[c + 1] : 0u;
    unsigned long long lo = (unsigned long long)w0 | ((unsigned long long)w1 << 32);
    unsigned long long win = lo >> o;
    if (o) win |= (unsigned long long)w2 << (64 - o);
    if (bit) {                       // fg pixel: nearest 0
        int d = ndist((~win) & validw);
        if (d < 0) d = far_search(w, x, 0);
        return d;
    } else {                         // bg pixel: nearest 1
        int d = ndist(win & validw);
        if (d < 0) d = far_search(w, x, 1);
        return -d;
    }
}

// Pass 1: one block = ROWS1 rows of one image. 320 threads.
__global__ void __launch_bounds__(NW)
hd_pass1_kernel(const float* __restrict__ pred,
                const float* __restrict__ tgt,
                float* __restrict__ out) {
    const int y0 = blockIdx.x * ROWS1;
    const int n = blockIdx.y;
    const int x = threadIdx.x;

    if (blockIdx.x == 0 && n == 0 && x == 0) out[0] = 0.0f;

    __shared__ unsigned int wp[ROWS1][NWORDS];
    __shared__ unsigned int wt[ROWS1][NWORDS];

    const int base = (n * NH + y0) * NW + x;

    // Front-load all inputs: 8 independent global loads, one latency exposure.
    float pv[ROWS1], tv[ROWS1];
#pragma unroll
    for (int k = 0; k < ROWS1; k++) {
        pv[k] = pred[base + k * NW];
        tv[k] = tgt[base + k * NW];
    }

    const int lane = x & 31, wid = x >> 5;
    int bp[ROWS1], bt[ROWS1];
#pragma unroll
    for (int k = 0; k < ROWS1; k++) {
        bp[k] = (pv[k] > 0.5f) ? 1 : 0;
        bt[k] = (tv[k] > 0.5f) ? 1 : 0;
        const unsigned int balp = __ballot_sync(0xffffffffu, bp[k]);
        const unsigned int balt = __ballot_sync(0xffffffffu, bt[k]);
        if (lane == 0) { wp[k][wid] = balp; wt[k][wid] = balt; }
    }

    __syncthreads();   // publish all rows

    if (x == 0) {
        unsigned int pa = 0u, ta = 0u;
#pragma unroll
        for (int k = 0; k < ROWS1; k++)
#pragma unroll
            for (int i = 0; i < NWORDS; i++) { pa |= wp[k][i]; ta |= wt[k][i]; }
        if (pa) atomicOr(&g_hasfg[0][n], 1);
        if (ta) atomicOr(&g_hasfg[1][n], 1);
    }

    unsigned long long validw = ~0ULL;
    if (x < 32)  validw <<= (32 - x);
    if (x > 288) validw &= (~0ULL >> (x - 288));

#pragma unroll
    for (int k = 0; k < ROWS1; k++) {
        const int cP = row_code(wp[k], wid, lane, validw, bp[k], x);
        const int cT = row_code(wt[k], wid, lane, validw, bt[k], x);
        g_code2[base + k * NW] = make_short2((short)cP, (short)cT);
    }
}

// R7-style shrinking-bound serial walk for one pixel (column x, row y).
// Returns bestP/bestT via references.
__device__ __forceinline__ void walk_pixel(const short2* __restrict__ colbase,
                                           int y, short2 c0,
                                           int& bestP_out, int& bestT_out) {
    const int cp = c0.x, ct = c0.y;
    const int sP = (cp > 0) ? 1 : -1;
    const int sT = (ct > 0) ? 1 : -1;
    const int aP = abs(cp), aT = abs(ct);
    int bestP = aP * aP;
    int bestT = aT * aT;
    int bmax = max(bestP, bestT);

    const int rUp = y;
    const int rDn = NH - 1 - y;
    const short2* up = colbase + (y - 1) * NW;
    const short2* dn = colbase + (y + 1) * NW;

    int r = 1, r2 = 1;
    while (r2 < bmax) {
        if (r <= rUp) {
            const short2 v = *up;
            const int dP = max(sP * (int)v.x, 0);
            const int dT = max(sT * (int)v.y, 0);
            bestP = min(bestP, dP * dP + r2);
            bestT = min(bestT, dT * dT + r2);
        }
        if (r <= rDn) {
            const short2 v = *dn;
            const int dP = max(sP * (int)v.x, 0);
            const int dT = max(sT * (int)v.y, 0);
            bestP = min(bestP, dP * dP + r2);
            bestT = min(bestT, dT * dT + r2);
        }
        up -= NW; dn += NW;
        bmax = max(bestP, bestT);
        r += 1;
        r2 += (r << 1) - 1;
    }
    bestP_out = bestP;
    bestT_out = bestT;
}

// Pass 2 + fused loss. One block = ROWS2 rows of one image, 320 threads.
// Amortizes prologue + reduction + atomic over 4 rows; front-loads 12
// independent input loads for MLP.
__global__ void __launch_bounds__(NW)
hd_pass2_kernel(const float* __restrict__ pred,
                const float* __restrict__ tgt,
                float* __restrict__ out) {
    const int y0 = blockIdx.x * ROWS2;
    const int n = blockIdx.y;
    const int x = threadIdx.x;

    const int plane = n * NH * NW;
    const int base = plane + y0 * NW + x;

    // Front-load all inputs for 4 rows: 12 independent loads.
    float pv[ROWS2], tv[ROWS2];
    short2 c0[ROWS2];
#pragma unroll
    for (int k = 0; k < ROWS2; k++) {
        pv[k] = pred[base + k * NW];
        tv[k] = tgt[base + k * NW];
        c0[k] = g_code2[base + k * NW];
    }
    const int hp = g_hasfg[0][n];
    const int ht = g_hasfg[1][n];

    const short2* colbase = g_code2 + plane + x;

    float acc = 0.0f;
#pragma unroll
    for (int k = 0; k < ROWS2; k++) {
        int bestP, bestT;
        walk_pixel(colbase, y0 + k, c0[k], bestP, bestT);
        const float dt2p = hp ? (float)bestP : 0.0f;
        const float dt2t = ht ? (float)bestT : 0.0f;
        const float e = pv[k] - tv[k];
        acc += e * e * (dt2p + dt2t);
    }
    acc *= INV_N;

    // One reduction + one atomic for 4 rows (1280 pixels).
#pragma unroll
    for (int off = 16; off > 0; off >>= 1)
        acc += __shfl_down_sync(0xffffffffu, acc, off);

    __shared__ float wsum[NW / 32];
    const int lane = x & 31;
    const int wid = x >> 5;
    if (lane == 0) wsum[wid] = acc;
    __syncthreads();
    if (x == 0) {
        float s = 0.0f;
#pragma unroll
        for (int i = 0; i < NW / 32; i++) s += wsum[i];
        atomicAdd(out, s);
    }
}

extern "C" void kernel_launch(void* const* d_in, const int* in_sizes, int n_in,
                              void* d_out, int out_size) {
    const float* pred = (const float*)d_in[0];
    const float* tgt  = (const float*)d_in[1];
    float* out = (float*)d_out;

    dim3 grid1(NH / ROWS1, NB);
    hd_pass1_kernel<<<grid1, NW>>>(pred, tgt, out);
    dim3 grid2(NH / ROWS2, NB);
    hd_pass2_kernel<<<grid2, NW>>>(pred, tgt, out);
}